// round 8
// baseline (speedup 1.0000x reference)
#include <cuda_runtime.h>
#include <cstdint>

#define NB 4
#define NC 64
#define NH 128
#define NW 128
#define NPIX (NH*NW)
#define NWIN 31
#define NL (NWIN*NWIN)

typedef unsigned long long u64;

// proj slot order: 0=ql 1=kh 2=vh 3=qh 4=kl 5=vl  (dir0 uses 0,1,2; dir1 uses 3,4,5)
__device__ float g_proj[6*NB*NC*NPIX];
__device__ float g_acc_l[NB*NC*NPIX];
__device__ float g_acc_h[NB*NC*NPIX];
__device__ float g_mean[NB*NC];
__device__ float g_sgate[NB*NC];

// ---------------- packed f32x2 helpers (proj/epi) ----------------
__device__ __forceinline__ u64 pk2(float lo, float hi) {
    u64 r;
    asm("mov.b64 %0,{%1,%2};" : "=l"(r) : "f"(lo), "f"(hi));
    return r;
}
__device__ __forceinline__ void upk2(float& lo, float& hi, u64 v) {
    asm("mov.b64 {%0,%1},%2;" : "=f"(lo), "=f"(hi) : "l"(v));
}
__device__ __forceinline__ u64 fma2(u64 a, u64 b, u64 c) {
    u64 d;
    asm("fma.rn.f32x2 %0,%1,%2,%3;" : "=l"(d) : "l"(a), "l"(b), "l"(c));
    return d;
}

// ---------------- tf32 mma helpers ----------------
__device__ __forceinline__ uint32_t tf32r(float f) {
    uint32_t r;
    asm("cvt.rna.tf32.f32 %0,%1;" : "=r"(r) : "f"(f));
    return r;
}
__device__ __forceinline__ float ex2(float x) {
    float r;
    asm("ex2.approx.f32 %0,%1;" : "=f"(r) : "f"(x));
    return r;
}
__device__ __forceinline__ void mma8(float* d, const uint32_t* a, uint32_t b0, uint32_t b1) {
    asm volatile(
        "mma.sync.aligned.m16n8k8.row.col.f32.tf32.tf32.f32 "
        "{%0,%1,%2,%3},{%4,%5,%6,%7},{%8,%9},{%0,%1,%2,%3};"
        : "+f"(d[0]), "+f"(d[1]), "+f"(d[2]), "+f"(d[3])
        : "r"(a[0]), "r"(a[1]), "r"(a[2]), "r"(a[3]), "r"(b0), "r"(b1));
}
// split a float into tf32 hi + tf32 lo
__device__ __forceinline__ void tsplit(float x, uint32_t& hi, uint32_t& lo) {
    hi = tf32r(x);
    lo = tf32r(x - __uint_as_float(hi));
}

// ---------------- SE: per-channel global mean ----------------
__global__ void mean_kernel(const float* __restrict__ high) {
    int bc = blockIdx.x;
    const float* p = high + (size_t)bc * NPIX;
    float s = 0.f;
    for (int i = threadIdx.x; i < NPIX; i += 256) s += p[i];
    __shared__ float red[256];
    red[threadIdx.x] = s; __syncthreads();
    for (int k = 128; k > 0; k >>= 1) {
        if (threadIdx.x < k) red[threadIdx.x] += red[threadIdx.x + k];
        __syncthreads();
    }
    if (threadIdx.x == 0) g_mean[bc] = red[0] * (1.f/NPIX);
}

// ---------------- SE: gate per (b,c) ----------------
__global__ void se_kernel(const float* __restrict__ w10, const float* __restrict__ w20,
                          const float* __restrict__ w11, const float* __restrict__ w21,
                          const float* __restrict__ w12, const float* __restrict__ w22) {
    int t = threadIdx.x;
    int b = t >> 6, c = t & 63;
    int g  = (c < 22) ? 0 : ((c < 43) ? 1 : 2);
    int of = (g == 0) ? 0 : ((g == 1) ? 22 : 43);
    int gc = (g == 0) ? 22 : 21;
    const float* w1 = (g==0) ? w10 : ((g==1) ? w11 : w12);
    const float* w2 = (g==0) ? w20 : ((g==1) ? w21 : w22);
    float h = 0.f;
    for (int j = 0; j < gc; j++) h += g_mean[b*64 + of + j] * w1[j];
    h = fmaxf(h, 0.f);
    float v = h * w2[c - of];
    g_sgate[t] = 1.f / (1.f + __expf(-v));
}

// ---------------- global projections (fma2; q-weights pre-scaled by 0.25*log2e) ----------------
#define WTS 68
#define QS 0.36067376022224085f
__global__ void __launch_bounds__(256,2) proj_kernel(
    const float* __restrict__ low, const float* __restrict__ high,
    const float* __restrict__ w_ql, const float* __restrict__ w_kh,
    const float* __restrict__ w_vh, const float* __restrict__ w_qh,
    const float* __restrict__ w_kl, const float* __restrict__ w_vl)
{
    extern __shared__ float sm[];
    float* xl = sm;            // 4096
    float* xh = sm + 4096;     // 4096
    float* wt = sm + 8192;     // 3 * 64*68

    int t = threadIdx.x;
    int pix0 = blockIdx.x * 64;
    int b = blockIdx.y;

    for (int i4 = t; i4 < 1024; i4 += 256) {
        int c = i4 >> 4, pp = (i4 & 15) * 4;
        size_t gi = (size_t)(b*NC + c)*NPIX + pix0 + pp;
        float4 vl = *(const float4*)(low + gi);
        float4 vh = *(const float4*)(high + gi);
        float gt = g_sgate[b*64 + c];
        vh.x *= gt; vh.y *= gt; vh.z *= gt; vh.w *= gt;
        *(float4*)(xl + c*64 + pp) = vl;
        *(float4*)(xh + c*64 + pp) = vh;
    }

    int ot = (t >> 4) << 2;
    int nb = (t & 15) << 2;

    for (int g = 0; g < 2; g++) {
        __syncthreads();
        const float* W0 = g ? w_kh : w_ql;
        const float* W1 = g ? w_vh : w_kl;
        const float* W2 = g ? w_qh : w_vl;
        for (int i = t; i < 12288; i += 256) {
            int p = i >> 12, j = i & 4095;
            int o = j >> 6, c = j & 63;
            const float* Wp = (p == 0) ? W0 : ((p == 1) ? W1 : W2);
            float wv = Wp[j];
            if ((g == 0 && p == 0) || (g == 1 && p == 2)) wv *= QS;
            wt[p*4352 + c*WTS + o] = wv;
        }
        __syncthreads();
        const float* Xs = g ? xh : xl;

        u64 acc2[3][4][2];
        #pragma unroll
        for (int p = 0; p < 3; p++)
            #pragma unroll
            for (int n = 0; n < 4; n++) { acc2[p][n][0] = 0ULL; acc2[p][n][1] = 0ULL; }

        #pragma unroll 2
        for (int c0 = 0; c0 < 64; c0 += 4) {
            #pragma unroll
            for (int k = 0; k < 4; k++) {
                float4 x4 = *(const float4*)(Xs + (c0+k)*64 + nb);
                u64 xd0 = pk2(x4.x, x4.x);
                u64 xd1 = pk2(x4.y, x4.y);
                u64 xd2 = pk2(x4.z, x4.z);
                u64 xd3 = pk2(x4.w, x4.w);
                #pragma unroll
                for (int p = 0; p < 3; p++) {
                    ulonglong2 w2v = *(const ulonglong2*)(wt + p*4352 + (c0+k)*WTS + ot);
                    acc2[p][0][0] = fma2(xd0, w2v.x, acc2[p][0][0]);
                    acc2[p][0][1] = fma2(xd0, w2v.y, acc2[p][0][1]);
                    acc2[p][1][0] = fma2(xd1, w2v.x, acc2[p][1][0]);
                    acc2[p][1][1] = fma2(xd1, w2v.y, acc2[p][1][1]);
                    acc2[p][2][0] = fma2(xd2, w2v.x, acc2[p][2][0]);
                    acc2[p][2][1] = fma2(xd2, w2v.y, acc2[p][2][1]);
                    acc2[p][3][0] = fma2(xd3, w2v.x, acc2[p][3][0]);
                    acc2[p][3][1] = fma2(xd3, w2v.y, acc2[p][3][1]);
                }
            }
        }
        int slots[3];
        slots[0] = g ? 1 : 0; slots[1] = g ? 2 : 4; slots[2] = g ? 3 : 5;
        #pragma unroll
        for (int p = 0; p < 3; p++) {
            float lo0[4], hi0[4], lo1[4], hi1[4];
            #pragma unroll
            for (int n = 0; n < 4; n++) {
                upk2(lo0[n], hi0[n], acc2[p][n][0]);
                upk2(lo1[n], hi1[n], acc2[p][n][1]);
            }
            size_t base = (size_t)slots[p]*NB*NC*NPIX + (size_t)(b*NC)*NPIX + pix0 + nb;
            *(float4*)(g_proj + base + (size_t)(ot+0)*NPIX) = make_float4(lo0[0],lo0[1],lo0[2],lo0[3]);
            *(float4*)(g_proj + base + (size_t)(ot+1)*NPIX) = make_float4(hi0[0],hi0[1],hi0[2],hi0[3]);
            *(float4*)(g_proj + base + (size_t)(ot+2)*NPIX) = make_float4(lo1[0],lo1[1],lo1[2],lo1[3]);
            *(float4*)(g_proj + base + (size_t)(ot+3)*NPIX) = make_float4(hi1[0],hi1[1],hi1[2],hi1[3]);
        }
    }
}

// ---------------- attention: tf32 MMA, K/V pre-converted to (hi,lo) uint2 in smem ----------------
// Per warp = one head. Same algebra as round 7 (sigma permutation chains S C-regs into AV
// B-fragments), but all K/V tf32 splits are done ONCE in a cooperative staging pass.
#define KVS 66    // uint2 row stride (64 cols + 2 pad -> 4-bank rotation per row)
#define HSZ (16*KVS)

__global__ void __launch_bounds__(128, 3) attn_kernel()
{
    extern __shared__ uint32_t smu[];
    uint2* k2 = (uint2*)smu;                 // 4 heads * 16d * KVS
    uint2* v2 = k2 + 4*HSZ;
    float* sinv = (float*)(smu + 4*4*HSZ);   // 256 floats

    int t = threadIdx.x;
    int l = blockIdx.x, dir = blockIdx.y, b = blockIdx.z;
    int y0 = (l / NWIN) * 4, x0 = (l % NWIN) * 4;

    // stage + convert K and V tiles (slots dir*3+1, dir*3+2)
    for (int i4 = t; i4 < 2048; i4 += 128) {
        int p = i4 >> 10, rem = i4 & 1023;       // p: 0=k 1=v
        int slot = dir*3 + 1 + p;
        int c = rem >> 4, q4 = rem & 15;         // c: global channel, q4: group of 4 pixels
        int r = q4 >> 1, cc = (q4 & 1) * 4;
        int n = r*8 + cc;
        size_t gi = ((size_t)slot*NB*NC + (size_t)(b*NC + c))*NPIX + (size_t)(y0 + r)*NW + x0 + cc;
        float4 v4 = *(const float4*)(g_proj + gi);
        uint2 e0, e1, e2, e3;
        tsplit(v4.x, e0.x, e0.y);
        tsplit(v4.y, e1.x, e1.y);
        tsplit(v4.z, e2.x, e2.y);
        tsplit(v4.w, e3.x, e3.y);
        uint2* dst = (p ? v2 : k2) + (c >> 4)*HSZ + (c & 15)*KVS + n;
        dst[0] = e0; dst[1] = e1; dst[2] = e2; dst[3] = e3;
    }
    __syncthreads();

    int h = t >> 5, lane = t & 31;
    int gid = lane >> 2, tig = lane & 3;
    int sig = (gid & 1) ? ((gid >> 1) + 4) : (gid >> 1);   // sigma(gid)

    const uint2* k2f = k2 + h*HSZ;
    const uint2* v2f = v2 + h*HSZ;
    const float* Qg = g_proj + ((size_t)(dir ? 3 : 0)*NB*NC + (size_t)(b*NC + h*16))*NPIX;
    float* gout = (dir ? g_acc_h : g_acc_l) + ((size_t)(b*NC + h*16))*NPIX;

    #pragma unroll
    for (int nt = 0; nt < 4; nt++) {
        int nbase = nt*16;
        size_t pA = (size_t)(y0 + 2*nt)*NW + x0 + gid;   // pixel for n = nbase+gid
        size_t pB = pA + NW;                              // pixel for n = nbase+gid+8

        // ---- Q A-fragments (hi/lo) from gmem, 2 d-chunks ----
        uint32_t qh[2][4], ql[2][4];
        #pragma unroll
        for (int kq = 0; kq < 2; kq++) {
            int d0 = kq*8 + tig;
            tsplit(Qg[(size_t)d0*NPIX     + pA], qh[kq][0], ql[kq][0]);
            tsplit(Qg[(size_t)d0*NPIX     + pB], qh[kq][1], ql[kq][1]);
            tsplit(Qg[(size_t)(d0+4)*NPIX + pA], qh[kq][2], ql[kq][2]);
            tsplit(Qg[(size_t)(d0+4)*NPIX + pB], qh[kq][3], ql[kq][3]);
        }

        float o0[4] = {0.f,0.f,0.f,0.f};   // O tile, n = nbase + 0..7
        float o1[4] = {0.f,0.f,0.f,0.f};   // O tile, n = nbase + 8..15
        float rs0 = 0.f, rs1 = 0.f;

        #pragma unroll
        for (int m8 = 0; m8 < 64; m8 += 8) {
            // ---- S tile [n16 x m8], 3-term tf32 ----
            float c[4] = {0.f,0.f,0.f,0.f};
            #pragma unroll
            for (int kq = 0; kq < 2; kq++) {
                uint2 kk0 = k2f[(kq*8+tig)*KVS   + m8 + sig];
                uint2 kk1 = k2f[(kq*8+tig+4)*KVS + m8 + sig];
                mma8(c, qh[kq], kk0.x, kk1.x);
                mma8(c, qh[kq], kk0.y, kk1.y);
                mma8(c, ql[kq], kk0.x, kk1.x);
            }
            // ---- exp, rowsum, split P ----
            float e0 = ex2(c[0]), e1 = ex2(c[1]), e2 = ex2(c[2]), e3 = ex2(c[3]);
            rs0 += e0 + e1;
            rs1 += e2 + e3;
            uint32_t ph[4], pl[4];
            tsplit(e0, ph[0], pl[0]);
            tsplit(e1, ph[1], pl[1]);
            tsplit(e2, ph[2], pl[2]);
            tsplit(e3, ph[3], pl[3]);
            // ---- V A-fragments (pre-converted) ----
            uint2 vv0 = v2f[gid*66     + m8 + tig    ];
            uint2 vv1 = v2f[(gid+8)*66 + m8 + tig    ];
            uint2 vv2 = v2f[gid*66     + m8 + tig + 4];
            uint2 vv3 = v2f[(gid+8)*66 + m8 + tig + 4];
            uint32_t vh[4] = {vv0.x, vv1.x, vv2.x, vv3.x};
            uint32_t vl[4] = {vv0.y, vv1.y, vv2.y, vv3.y};
            // ---- AV: O[d16 x n8] += V * P^T (3-term) ----
            mma8(o0, vh, ph[0], ph[1]);
            mma8(o0, vl, ph[0], ph[1]);
            mma8(o0, vh, pl[0], pl[1]);
            mma8(o1, vh, ph[2], ph[3]);
            mma8(o1, vl, ph[2], ph[3]);
            mma8(o1, vh, pl[2], pl[3]);
        }
        // ---- softmax denominators: reduce across the 4 tig lanes ----
        rs0 += __shfl_xor_sync(0xffffffffu, rs0, 1);
        rs0 += __shfl_xor_sync(0xffffffffu, rs0, 2);
        rs1 += __shfl_xor_sync(0xffffffffu, rs1, 1);
        rs1 += __shfl_xor_sync(0xffffffffu, rs1, 2);
        if (tig == 0) {
            sinv[h*64 + nbase + gid]     = 1.f / rs0;
            sinv[h*64 + nbase + gid + 8] = 1.f / rs1;
        }
        __syncwarp();
        // ---- normalize + atomic fold ----
        #pragma unroll
        for (int jt = 0; jt < 2; jt++) {
            const float* ot = jt ? o1 : o0;
            int n0 = nbase + jt*8 + 2*tig;
            float inv0 = sinv[h*64 + n0];
            float inv1 = sinv[h*64 + n0 + 1];
            size_t pix0 = (size_t)(y0 + (n0 >> 3))*NW + x0 + (n0 & 7);
            size_t pix1 = (size_t)(y0 + ((n0+1) >> 3))*NW + x0 + ((n0+1) & 7);
            atomicAdd(gout + (size_t)gid*NPIX     + pix0, ot[0]*inv0);
            atomicAdd(gout + (size_t)gid*NPIX     + pix1, ot[1]*inv1);
            atomicAdd(gout + (size_t)(gid+8)*NPIX + pix0, ot[2]*inv0);
            atomicAdd(gout + (size_t)(gid+8)*NPIX + pix1, ot[3]*inv1);
        }
    }
}

// ---------------- epilogue: normalize fold, 1x1 proj + residual ----------------
__device__ __forceinline__ int covdim(int y) {
    int imin = (y >= 8) ? ((y - 4) >> 2) : 0;
    int imax = y >> 2; if (imax > 30) imax = 30;
    return imax - imin + 1;
}

#define WST 72

__global__ void __launch_bounds__(256) epi_kernel(
    const float* __restrict__ low, const float* __restrict__ high,
    const float* __restrict__ wpl, const float* __restrict__ wph,
    float* __restrict__ out)
{
    extern __shared__ float sm[];
    float* tl = sm;                    // 8192
    float* th = sm + 8192;             // 8192
    float* wl = sm + 16384;            // 64*WST
    float* wh = sm + 16384 + 64*WST;   // 64*WST

    int t = threadIdx.x;
    int y = blockIdx.x, b = blockIdx.y;
    float cy = (float)covdim(y);

    for (int i = t; i < 8192; i += 256) {
        int c = i >> 7, x = i & 127;
        float ic = 1.f / (cy * (float)covdim(x));
        size_t gi = ((size_t)(b*NC + c)*NH + y)*NW + x;
        tl[i] = g_acc_l[gi] * ic;
        th[i] = g_acc_h[gi] * ic;
    }
    for (int i = t; i < 4096; i += 256) {
        int o = i >> 6, c = i & 63;
        wl[c*WST + o] = wpl[i];
        wh[c*WST + o] = wph[i];
    }
    __syncthreads();

    int x = t & 127, og = (t >> 7) * 32;
    u64 rl2[16], rh2[16];
    #pragma unroll
    for (int j = 0; j < 16; j++) { rl2[j] = 0ULL; rh2[j] = 0ULL; }

    for (int c = 0; c < 64; c++) {
        float tv = tl[c*128 + x];
        float hv = th[c*128 + x];
        u64 tv2 = pk2(tv, tv);
        u64 hv2 = pk2(hv, hv);
        const ulonglong2* wlr = (const ulonglong2*)(wl + c*WST + og);
        const ulonglong2* whr = (const ulonglong2*)(wh + c*WST + og);
        #pragma unroll
        for (int o4 = 0; o4 < 8; o4++) {
            ulonglong2 a2 = wlr[o4];
            ulonglong2 b2 = whr[o4];
            rl2[o4*2]   = fma2(tv2, a2.x, rl2[o4*2]);
            rl2[o4*2+1] = fma2(tv2, a2.y, rl2[o4*2+1]);
            rh2[o4*2]   = fma2(hv2, b2.x, rh2[o4*2]);
            rh2[o4*2+1] = fma2(hv2, b2.y, rh2[o4*2+1]);
        }
    }
    size_t half = (size_t)NB*NC*NPIX;
    #pragma unroll
    for (int j = 0; j < 16; j++) {
        float a, bb; upk2(a, bb, rl2[j]);
        float c2, d2; upk2(c2, d2, rh2[j]);
        int o0 = og + j*2;
        size_t gi0 = ((size_t)(b*NC + o0)*NH + y)*NW + x;
        size_t gi1 = ((size_t)(b*NC + o0 + 1)*NH + y)*NW + x;
        out[gi0]        = low[gi0]  + a;
        out[gi1]        = low[gi1]  + bb;
        out[half + gi0] = high[gi0] + c2;
        out[half + gi1] = high[gi1] + d2;
    }
}

extern "C" void kernel_launch(void* const* d_in, const int* in_sizes, int n_in,
                              void* d_out, int out_size)
{
    (void)in_sizes; (void)n_in; (void)out_size;
    const float* low  = (const float*)d_in[0];
    const float* high = (const float*)d_in[1];
    const float* w_ql = (const float*)d_in[2];
    const float* w_kh = (const float*)d_in[3];
    const float* w_vh = (const float*)d_in[4];
    const float* w_qh = (const float*)d_in[5];
    const float* w_kl = (const float*)d_in[6];
    const float* w_vl = (const float*)d_in[7];
    const float* wpl  = (const float*)d_in[8];
    const float* wph  = (const float*)d_in[9];

    void* pl; cudaGetSymbolAddress(&pl, g_acc_l);
    void* ph; cudaGetSymbolAddress(&ph, g_acc_h);
    cudaMemsetAsync(pl, 0, sizeof(float)*(size_t)NB*NC*NPIX);
    cudaMemsetAsync(ph, 0, sizeof(float)*(size_t)NB*NC*NPIX);

    int attn_smem = (4*4*(16*KVS) + 256) * 4;   // k2+v2 (uint2 as 2 words) + sinv

    cudaFuncSetAttribute(proj_kernel, cudaFuncAttributeMaxDynamicSharedMemorySize, (8192+13056)*4);
    cudaFuncSetAttribute(attn_kernel, cudaFuncAttributeMaxDynamicSharedMemorySize, attn_smem);
    cudaFuncSetAttribute(epi_kernel,  cudaFuncAttributeMaxDynamicSharedMemorySize, (16384 + 2*64*WST)*4);

    mean_kernel<<<NB*NC, 256>>>(high);
    se_kernel<<<1, 256>>>((const float*)d_in[10], (const float*)d_in[11],
                          (const float*)d_in[12], (const float*)d_in[13],
                          (const float*)d_in[14], (const float*)d_in[15]);
    proj_kernel<<<dim3(NPIX/64, NB), 256, (8192+13056)*4>>>(low, high, w_ql, w_kh, w_vh, w_qh, w_kl, w_vl);
    attn_kernel<<<dim3(NL, 2, NB), 128, attn_smem>>>();
    epi_kernel<<<dim3(NH, NB), 256, (16384 + 2*64*WST)*4>>>(low, high, wpl, wph, (float*)d_out);
}

// round 10
// speedup vs baseline: 1.1081x; 1.1081x over previous
#include <cuda_runtime.h>

#define NB 4
#define NC 64
#define NH 128
#define NW 128
#define NPIX (NH*NW)
#define NWIN 31
#define NL (NWIN*NWIN)

typedef unsigned long long u64;

// proj slot order: 0=ql 1=kh 2=vh 3=qh 4=kl 5=vl  (dir0 uses 0,1,2; dir1 uses 3,4,5)
__device__ float g_proj[6*NB*NC*NPIX];
__device__ float g_acc_l[NB*NC*NPIX];
__device__ float g_acc_h[NB*NC*NPIX];
__device__ float g_mean[NB*NC];
__device__ float g_sgate[NB*NC];

// ---------------- packed f32x2 helpers ----------------
__device__ __forceinline__ u64 pk2(float lo, float hi) {
    u64 r;
    asm("mov.b64 %0,{%1,%2};" : "=l"(r) : "f"(lo), "f"(hi));
    return r;
}
__device__ __forceinline__ void upk2(float& lo, float& hi, u64 v) {
    asm("mov.b64 {%0,%1},%2;" : "=f"(lo), "=f"(hi) : "l"(v));
}
__device__ __forceinline__ u64 fma2(u64 a, u64 b, u64 c) {
    u64 d;
    asm("fma.rn.f32x2 %0,%1,%2,%3;" : "=l"(d) : "l"(a), "l"(b), "l"(c));
    return d;
}
__device__ __forceinline__ u64 add2(u64 a, u64 b) {
    u64 d;
    asm("add.rn.f32x2 %0,%1,%2;" : "=l"(d) : "l"(a), "l"(b));
    return d;
}

// ---------------- SE: per-channel global mean ----------------
__global__ void mean_kernel(const float* __restrict__ high) {
    int bc = blockIdx.x;
    const float* p = high + (size_t)bc * NPIX;
    float s = 0.f;
    for (int i = threadIdx.x; i < NPIX; i += 256) s += p[i];
    __shared__ float red[256];
    red[threadIdx.x] = s; __syncthreads();
    for (int k = 128; k > 0; k >>= 1) {
        if (threadIdx.x < k) red[threadIdx.x] += red[threadIdx.x + k];
        __syncthreads();
    }
    if (threadIdx.x == 0) g_mean[bc] = red[0] * (1.f/NPIX);
}

// ---------------- SE: gate per (b,c) ----------------
__global__ void se_kernel(const float* __restrict__ w10, const float* __restrict__ w20,
                          const float* __restrict__ w11, const float* __restrict__ w21,
                          const float* __restrict__ w12, const float* __restrict__ w22) {
    int t = threadIdx.x;
    int b = t >> 6, c = t & 63;
    int g  = (c < 22) ? 0 : ((c < 43) ? 1 : 2);
    int of = (g == 0) ? 0 : ((g == 1) ? 22 : 43);
    int gc = (g == 0) ? 22 : 21;
    const float* w1 = (g==0) ? w10 : ((g==1) ? w11 : w12);
    const float* w2 = (g==0) ? w20 : ((g==1) ? w21 : w22);
    float h = 0.f;
    for (int j = 0; j < gc; j++) h += g_mean[b*64 + of + j] * w1[j];
    h = fmaxf(h, 0.f);
    float v = h * w2[c - of];
    g_sgate[t] = 1.f / (1.f + __expf(-v));
}

// ---------------- projections: 3 stages of 2 weights; 67KB smem -> 3 blocks/SM ----------------
#define WTS 68
#define QS 0.36067376022224085f
__global__ void __launch_bounds__(256,3) proj_kernel(
    const float* __restrict__ low, const float* __restrict__ high,
    const float* __restrict__ w_ql, const float* __restrict__ w_kh,
    const float* __restrict__ w_vh, const float* __restrict__ w_qh,
    const float* __restrict__ w_kl, const float* __restrict__ w_vl)
{
    extern __shared__ float sm[];
    float* xl = sm;            // 4096
    float* xh = sm + 4096;     // 4096
    float* wb = sm + 8192;     // 2 * 64*68 = 8704

    int t = threadIdx.x;
    int pix0 = blockIdx.x * 64;
    int b = blockIdx.y;

    for (int i4 = t; i4 < 1024; i4 += 256) {
        int c = i4 >> 4, pp = (i4 & 15) * 4;
        size_t gi = (size_t)(b*NC + c)*NPIX + pix0 + pp;
        float4 vl = *(const float4*)(low + gi);
        float4 vh = *(const float4*)(high + gi);
        float gt = g_sgate[b*64 + c];
        vh.x *= gt; vh.y *= gt; vh.z *= gt; vh.w *= gt;
        *(float4*)(xl + c*64 + pp) = vl;
        *(float4*)(xh + c*64 + pp) = vh;
    }

    int ot = (t >> 4) << 2;
    int nb = (t & 15) << 2;

    // s0: (0=ql[xl,QS], 4=kl[xl])   s1: (1=kh[xh], 2=vh[xh])   s2: (5=vl[xl], 3=qh[xh,QS])
    const float* WA[3]; const float* WB[3];
    WA[0] = w_ql; WB[0] = w_kl;
    WA[1] = w_kh; WB[1] = w_vh;
    WA[2] = w_vl; WB[2] = w_qh;
    const int slotA[3] = {0, 1, 5};
    const int slotB[3] = {4, 2, 3};

    for (int s = 0; s < 3; s++) {
        __syncthreads();
        bool scaleA = (s == 0), scaleB = (s == 2);
        for (int i = t; i < 8192; i += 256) {
            int p = i >> 12, j = i & 4095;
            int o = j >> 6, c = j & 63;
            float wv = (p == 0) ? WA[s][j] : WB[s][j];
            if ((p == 0 && scaleA) || (p == 1 && scaleB)) wv *= QS;
            wb[p*4352 + c*WTS + o] = wv;
        }
        __syncthreads();

        const float* XA = (s == 2) ? xl : ((s == 0) ? xl : xh);
        const float* XB = (s == 2) ? xh : ((s == 0) ? xl : xh);
        bool sameX = (s != 2);

        u64 acc2[2][4][2];
        #pragma unroll
        for (int p = 0; p < 2; p++)
            #pragma unroll
            for (int n = 0; n < 4; n++) { acc2[p][n][0] = 0ULL; acc2[p][n][1] = 0ULL; }

        if (sameX) {
            #pragma unroll 4
            for (int c = 0; c < 64; c++) {
                float4 x4 = *(const float4*)(XA + c*64 + nb);
                u64 xd0 = pk2(x4.x, x4.x);
                u64 xd1 = pk2(x4.y, x4.y);
                u64 xd2 = pk2(x4.z, x4.z);
                u64 xd3 = pk2(x4.w, x4.w);
                #pragma unroll
                for (int p = 0; p < 2; p++) {
                    ulonglong2 w2v = *(const ulonglong2*)(wb + p*4352 + c*WTS + ot);
                    acc2[p][0][0] = fma2(xd0, w2v.x, acc2[p][0][0]);
                    acc2[p][0][1] = fma2(xd0, w2v.y, acc2[p][0][1]);
                    acc2[p][1][0] = fma2(xd1, w2v.x, acc2[p][1][0]);
                    acc2[p][1][1] = fma2(xd1, w2v.y, acc2[p][1][1]);
                    acc2[p][2][0] = fma2(xd2, w2v.x, acc2[p][2][0]);
                    acc2[p][2][1] = fma2(xd2, w2v.y, acc2[p][2][1]);
                    acc2[p][3][0] = fma2(xd3, w2v.x, acc2[p][3][0]);
                    acc2[p][3][1] = fma2(xd3, w2v.y, acc2[p][3][1]);
                }
            }
        } else {
            #pragma unroll 4
            for (int c = 0; c < 64; c++) {
                float4 xa4 = *(const float4*)(XA + c*64 + nb);
                float4 xb4 = *(const float4*)(XB + c*64 + nb);
                u64 xa0 = pk2(xa4.x, xa4.x), xa1 = pk2(xa4.y, xa4.y);
                u64 xa2 = pk2(xa4.z, xa4.z), xa3 = pk2(xa4.w, xa4.w);
                u64 xb0 = pk2(xb4.x, xb4.x), xb1 = pk2(xb4.y, xb4.y);
                u64 xb2 = pk2(xb4.z, xb4.z), xb3 = pk2(xb4.w, xb4.w);
                ulonglong2 wa = *(const ulonglong2*)(wb + c*WTS + ot);
                ulonglong2 wv = *(const ulonglong2*)(wb + 4352 + c*WTS + ot);
                acc2[0][0][0] = fma2(xa0, wa.x, acc2[0][0][0]);
                acc2[0][0][1] = fma2(xa0, wa.y, acc2[0][0][1]);
                acc2[0][1][0] = fma2(xa1, wa.x, acc2[0][1][0]);
                acc2[0][1][1] = fma2(xa1, wa.y, acc2[0][1][1]);
                acc2[0][2][0] = fma2(xa2, wa.x, acc2[0][2][0]);
                acc2[0][2][1] = fma2(xa2, wa.y, acc2[0][2][1]);
                acc2[0][3][0] = fma2(xa3, wa.x, acc2[0][3][0]);
                acc2[0][3][1] = fma2(xa3, wa.y, acc2[0][3][1]);
                acc2[1][0][0] = fma2(xb0, wv.x, acc2[1][0][0]);
                acc2[1][0][1] = fma2(xb0, wv.y, acc2[1][0][1]);
                acc2[1][1][0] = fma2(xb1, wv.x, acc2[1][1][0]);
                acc2[1][1][1] = fma2(xb1, wv.y, acc2[1][1][1]);
                acc2[1][2][0] = fma2(xb2, wv.x, acc2[1][2][0]);
                acc2[1][2][1] = fma2(xb2, wv.y, acc2[1][2][1]);
                acc2[1][3][0] = fma2(xb3, wv.x, acc2[1][3][0]);
                acc2[1][3][1] = fma2(xb3, wv.y, acc2[1][3][1]);
            }
        }

        int sl[2]; sl[0] = slotA[s]; sl[1] = slotB[s];
        #pragma unroll
        for (int p = 0; p < 2; p++) {
            float lo0[4], hi0[4], lo1[4], hi1[4];
            #pragma unroll
            for (int n = 0; n < 4; n++) {
                upk2(lo0[n], hi0[n], acc2[p][n][0]);
                upk2(lo1[n], hi1[n], acc2[p][n][1]);
            }
            size_t base = (size_t)sl[p]*NB*NC*NPIX + (size_t)(b*NC)*NPIX + pix0 + nb;
            *(float4*)(g_proj + base + (size_t)(ot+0)*NPIX) = make_float4(lo0[0],lo0[1],lo0[2],lo0[3]);
            *(float4*)(g_proj + base + (size_t)(ot+1)*NPIX) = make_float4(hi0[0],hi0[1],hi0[2],hi0[3]);
            *(float4*)(g_proj + base + (size_t)(ot+2)*NPIX) = make_float4(lo1[0],lo1[1],lo1[2],lo1[3]);
            *(float4*)(g_proj + base + (size_t)(ot+3)*NPIX) = make_float4(hi1[0],hi1[1],hi1[2],hi1[3]);
        }
    }
}

// ---------------- attention: round-5/6 FFMA version (best known) ----------------
__global__ void __launch_bounds__(128, 4) attn_kernel()
{
    extern __shared__ float Y[];  // q[4096] k[4096] v[4096]

    int t = threadIdx.x;
    int l = blockIdx.x, dir = blockIdx.y, b = blockIdx.z;
    int y0 = (l / NWIN) * 4, x0 = (l % NWIN) * 4;

    for (int i4 = t; i4 < 3072; i4 += 128) {
        int p = i4 >> 10, rem = i4 & 1023;
        int slot = dir*3 + p;
        int c = rem >> 4, q4 = rem & 15;
        int r = q4 >> 1, cc = (q4 & 1) * 4;
        size_t gi = ((size_t)slot*NB*NC + (size_t)(b*NC + c))*NPIX + (size_t)(y0 + r)*NW + x0 + cc;
        *(float4*)(Y + p*4096 + c*64 + r*8 + cc) = *(const float4*)(g_proj + gi);
    }
    __syncthreads();

    int h = t >> 5, lane = t & 31;
    int nA = lane, nB = lane + 32;
    size_t pixA = (size_t)(y0 + (nA >> 3))*NW + x0 + (nA & 7);
    size_t pixB = (size_t)(y0 + (nB >> 3))*NW + x0 + (nB & 7);

    const float* Yq = Y + h*1024;
    const float* Yk = Y + 4096 + h*1024;
    const float* Yv = Y + 8192 + h*1024;
    float* gout = (dir ? g_acc_h : g_acc_l) + ((size_t)(b*NC + h*16))*NPIX;

    u64 accA[16], accB[16];
    #pragma unroll
    for (int j = 0; j < 16; j++) { accA[j] = 0ULL; accB[j] = 0ULL; }
    u64 sumA2 = 0ULL, sumB2 = 0ULL;

    #pragma unroll
    for (int ch = 0; ch < 4; ch++) {
        u64 lgA[8], lgB[8];
        #pragma unroll
        for (int j = 0; j < 8; j++) { lgA[j] = 0ULL; lgB[j] = 0ULL; }

        #pragma unroll
        for (int dd = 0; dd < 16; dd++) {
            float qa = Yq[dd*64 + nA];
            float qb = Yq[dd*64 + nB];
            u64 qa2 = pk2(qa, qa);
            u64 qb2 = pk2(qb, qb);
            const ulonglong2* kr = (const ulonglong2*)(Yk + dd*64 + ch*16);
            #pragma unroll
            for (int j2 = 0; j2 < 4; j2++) {
                ulonglong2 kk = kr[j2];
                lgA[j2*2]   = fma2(qa2, kk.x, lgA[j2*2]);
                lgA[j2*2+1] = fma2(qa2, kk.y, lgA[j2*2+1]);
                lgB[j2*2]   = fma2(qb2, kk.x, lgB[j2*2]);
                lgB[j2*2+1] = fma2(qb2, kk.y, lgB[j2*2+1]);
            }
        }
        #pragma unroll
        for (int j = 0; j < 8; j++) {
            float a, bb; upk2(a, bb, lgA[j]);
            lgA[j] = pk2(exp2f(a), exp2f(bb));
            sumA2 = add2(sumA2, lgA[j]);
            float c2, d2; upk2(c2, d2, lgB[j]);
            lgB[j] = pk2(exp2f(c2), exp2f(d2));
            sumB2 = add2(sumB2, lgB[j]);
        }
        #pragma unroll
        for (int dd = 0; dd < 16; dd++) {
            const ulonglong2* vr = (const ulonglong2*)(Yv + dd*64 + ch*16);
            u64 aA = accA[dd], aB = accB[dd];
            #pragma unroll
            for (int j2 = 0; j2 < 4; j2++) {
                ulonglong2 vv = vr[j2];
                aA = fma2(lgA[j2*2],   vv.x, aA);
                aA = fma2(lgA[j2*2+1], vv.y, aA);
                aB = fma2(lgB[j2*2],   vv.x, aB);
                aB = fma2(lgB[j2*2+1], vv.y, aB);
            }
            accA[dd] = aA; accB[dd] = aB;
        }
    }
    float sa0, sa1, sb0, sb1;
    upk2(sa0, sa1, sumA2);
    upk2(sb0, sb1, sumB2);
    float invA = 1.f / (sa0 + sa1);
    float invB = 1.f / (sb0 + sb1);
    #pragma unroll
    for (int dd = 0; dd < 16; dd++) {
        float a, bb; upk2(a, bb, accA[dd]);
        float c, d; upk2(c, d, accB[dd]);
        atomicAdd(gout + (size_t)dd*NPIX + pixA, (a + bb) * invA);
        atomicAdd(gout + (size_t)dd*NPIX + pixB, (c + d) * invB);
    }
}

// ---------------- epilogue: streaming (weights-only smem), 512 blocks ----------------
__device__ __forceinline__ int covdim(int y) {
    int imin = (y >= 8) ? ((y - 4) >> 2) : 0;
    int imax = y >> 2; if (imax > 30) imax = 30;
    return imax - imin + 1;
}

__global__ void __launch_bounds__(256) epi_kernel(
    const float* __restrict__ low, const float* __restrict__ high,
    const float* __restrict__ wpl, const float* __restrict__ wph,
    float* __restrict__ out)
{
    __shared__ float wl[64*WTS];
    __shared__ float wh[64*WTS];

    int t = threadIdx.x;
    int chunk = blockIdx.x;            // 512 chunks: 128 per batch, 128 pixels each
    int b = chunk >> 7;
    int pix0 = (chunk & 127) * 128;

    for (int i = t; i < 4096; i += 256) {
        int o = i >> 6, c = i & 63;
        wl[c*WTS + o] = wpl[i];
        wh[c*WTS + o] = wph[i];
    }
    __syncthreads();

    int px = t & 127, og = (t >> 7) * 32;
    int pix = pix0 + px;
    int y = pix >> 7, x = pix & 127;
    float ic = 1.f / ((float)covdim(y) * (float)covdim(x));

    const float* al = g_acc_l + (size_t)(b*NC)*NPIX + pix;
    const float* ah = g_acc_h + (size_t)(b*NC)*NPIX + pix;

    u64 rl2[16], rh2[16];
    #pragma unroll
    for (int j = 0; j < 16; j++) { rl2[j] = 0ULL; rh2[j] = 0ULL; }

    #pragma unroll 4
    for (int c = 0; c < 64; c++) {
        float tv = al[(size_t)c*NPIX] * ic;
        float hv = ah[(size_t)c*NPIX] * ic;
        u64 tv2 = pk2(tv, tv);
        u64 hv2 = pk2(hv, hv);
        const ulonglong2* wlr = (const ulonglong2*)(wl + c*WTS + og);
        const ulonglong2* whr = (const ulonglong2*)(wh + c*WTS + og);
        #pragma unroll
        for (int o4 = 0; o4 < 8; o4++) {
            ulonglong2 a2 = wlr[o4];
            ulonglong2 b2 = whr[o4];
            rl2[o4*2]   = fma2(tv2, a2.x, rl2[o4*2]);
            rl2[o4*2+1] = fma2(tv2, a2.y, rl2[o4*2+1]);
            rh2[o4*2]   = fma2(hv2, b2.x, rh2[o4*2]);
            rh2[o4*2+1] = fma2(hv2, b2.y, rh2[o4*2+1]);
        }
    }
    size_t half = (size_t)NB*NC*NPIX;
    #pragma unroll
    for (int j = 0; j < 16; j++) {
        float a, bb; upk2(a, bb, rl2[j]);
        float c2, d2; upk2(c2, d2, rh2[j]);
        int o0 = og + j*2;
        size_t gi0 = (size_t)(b*NC + o0)*NPIX + pix;
        size_t gi1 = (size_t)(b*NC + o0 + 1)*NPIX + pix;
        out[gi0]        = low[gi0]  + a;
        out[gi1]        = low[gi1]  + bb;
        out[half + gi0] = high[gi0] + c2;
        out[half + gi1] = high[gi1] + d2;
    }
}

extern "C" void kernel_launch(void* const* d_in, const int* in_sizes, int n_in,
                              void* d_out, int out_size)
{
    (void)in_sizes; (void)n_in; (void)out_size;
    const float* low  = (const float*)d_in[0];
    const float* high = (const float*)d_in[1];
    const float* w_ql = (const float*)d_in[2];
    const float* w_kh = (const float*)d_in[3];
    const float* w_vh = (const float*)d_in[4];
    const float* w_qh = (const float*)d_in[5];
    const float* w_kl = (const float*)d_in[6];
    const float* w_vl = (const float*)d_in[7];
    const float* wpl  = (const float*)d_in[8];
    const float* wph  = (const float*)d_in[9];

    void* pl; cudaGetSymbolAddress(&pl, g_acc_l);
    void* ph; cudaGetSymbolAddress(&ph, g_acc_h);
    cudaMemsetAsync(pl, 0, sizeof(float)*(size_t)NB*NC*NPIX);
    cudaMemsetAsync(ph, 0, sizeof(float)*(size_t)NB*NC*NPIX);

    int proj_smem = (8192 + 8704) * 4;   // 67.6 KB

    cudaFuncSetAttribute(proj_kernel, cudaFuncAttributeMaxDynamicSharedMemorySize, proj_smem);
    cudaFuncSetAttribute(attn_kernel, cudaFuncAttributeMaxDynamicSharedMemorySize, 12288*4);

    mean_kernel<<<NB*NC, 256>>>(high);
    se_kernel<<<1, 256>>>((const float*)d_in[10], (const float*)d_in[11],
                          (const float*)d_in[12], (const float*)d_in[13],
                          (const float*)d_in[14], (const float*)d_in[15]);
    proj_kernel<<<dim3(NPIX/64, NB), 256, proj_smem>>>(low, high, w_ql, w_kh, w_vh, w_qh, w_kl, w_vl);
    attn_kernel<<<dim3(NL, 2, NB), 128, 12288*4>>>();
    epi_kernel<<<512, 256>>>(low, high, wpl, wph, (float*)d_out);
}

// round 11
// speedup vs baseline: 1.2169x; 1.0981x over previous
#include <cuda_runtime.h>
#include <cstdint>

#define NB 4
#define NC 64
#define NH 128
#define NW 128
#define NPIX (NH*NW)
#define NWIN 31
#define NL (NWIN*NWIN)

typedef unsigned long long u64;

// proj slot order: 0=ql 1=kh 2=vh 3=qh 4=kl 5=vl  (dir0 uses 0,1,2; dir1 uses 3,4,5)
__device__ float g_proj[6*NB*NC*NPIX];
__device__ float g_acc_l[NB*NC*NPIX];
__device__ float g_acc_h[NB*NC*NPIX];
__device__ float g_mean[NB*NC];
__device__ float g_sgate[NB*NC];

// ---------------- packed f32x2 helpers ----------------
__device__ __forceinline__ u64 pk2(float lo, float hi) {
    u64 r;
    asm("mov.b64 %0,{%1,%2};" : "=l"(r) : "f"(lo), "f"(hi));
    return r;
}
__device__ __forceinline__ void upk2(float& lo, float& hi, u64 v) {
    asm("mov.b64 {%0,%1},%2;" : "=f"(lo), "=f"(hi) : "l"(v));
}
__device__ __forceinline__ u64 fma2(u64 a, u64 b, u64 c) {
    u64 d;
    asm("fma.rn.f32x2 %0,%1,%2,%3;" : "=l"(d) : "l"(a), "l"(b), "l"(c));
    return d;
}

// ---------------- tf32 mma helpers ----------------
__device__ __forceinline__ uint32_t tf32r(float f) {
    uint32_t r;
    asm("cvt.rna.tf32.f32 %0,%1;" : "=r"(r) : "f"(f));
    return r;
}
__device__ __forceinline__ float ex2(float x) {
    float r;
    asm("ex2.approx.f32 %0,%1;" : "=f"(r) : "f"(x));
    return r;
}
__device__ __forceinline__ void mma8(float* d, const uint32_t* a, uint32_t b0, uint32_t b1) {
    asm volatile(
        "mma.sync.aligned.m16n8k8.row.col.f32.tf32.tf32.f32 "
        "{%0,%1,%2,%3},{%4,%5,%6,%7},{%8,%9},{%0,%1,%2,%3};"
        : "+f"(d[0]), "+f"(d[1]), "+f"(d[2]), "+f"(d[3])
        : "r"(a[0]), "r"(a[1]), "r"(a[2]), "r"(a[3]), "r"(b0), "r"(b1));
}
__device__ __forceinline__ void tsplit(float x, uint32_t& hi, uint32_t& lo) {
    hi = tf32r(x);
    lo = tf32r(x - __uint_as_float(hi));
}

// ---------------- SE: per-channel global mean ----------------
__global__ void mean_kernel(const float* __restrict__ high) {
    int bc = blockIdx.x;
    const float* p = high + (size_t)bc * NPIX;
    float s = 0.f;
    for (int i = threadIdx.x; i < NPIX; i += 256) s += p[i];
    __shared__ float red[256];
    red[threadIdx.x] = s; __syncthreads();
    for (int k = 128; k > 0; k >>= 1) {
        if (threadIdx.x < k) red[threadIdx.x] += red[threadIdx.x + k];
        __syncthreads();
    }
    if (threadIdx.x == 0) g_mean[bc] = red[0] * (1.f/NPIX);
}

// ---------------- SE: gate per (b,c) ----------------
__global__ void se_kernel(const float* __restrict__ w10, const float* __restrict__ w20,
                          const float* __restrict__ w11, const float* __restrict__ w21,
                          const float* __restrict__ w12, const float* __restrict__ w22) {
    int t = threadIdx.x;
    int b = t >> 6, c = t & 63;
    int g  = (c < 22) ? 0 : ((c < 43) ? 1 : 2);
    int of = (g == 0) ? 0 : ((g == 1) ? 22 : 43);
    int gc = (g == 0) ? 22 : 21;
    const float* w1 = (g==0) ? w10 : ((g==1) ? w11 : w12);
    const float* w2 = (g==0) ? w20 : ((g==1) ? w21 : w22);
    float h = 0.f;
    for (int j = 0; j < gc; j++) h += g_mean[b*64 + of + j] * w1[j];
    h = fmaxf(h, 0.f);
    float v = h * w2[c - of];
    g_sgate[t] = 1.f / (1.f + __expf(-v));
}

// ---------------- projections: 3 stages of 2 weights; 67KB smem -> 3 blocks/SM ----------------
#define WTS 68
#define QS 0.36067376022224085f
__global__ void __launch_bounds__(256,3) proj_kernel(
    const float* __restrict__ low, const float* __restrict__ high,
    const float* __restrict__ w_ql, const float* __restrict__ w_kh,
    const float* __restrict__ w_vh, const float* __restrict__ w_qh,
    const float* __restrict__ w_kl, const float* __restrict__ w_vl)
{
    extern __shared__ float sm[];
    float* xl = sm;            // 4096
    float* xh = sm + 4096;     // 4096
    float* wb = sm + 8192;     // 2 * 64*68 = 8704

    int t = threadIdx.x;
    int pix0 = blockIdx.x * 64;
    int b = blockIdx.y;

    for (int i4 = t; i4 < 1024; i4 += 256) {
        int c = i4 >> 4, pp = (i4 & 15) * 4;
        size_t gi = (size_t)(b*NC + c)*NPIX + pix0 + pp;
        float4 vl = *(const float4*)(low + gi);
        float4 vh = *(const float4*)(high + gi);
        float gt = g_sgate[b*64 + c];
        vh.x *= gt; vh.y *= gt; vh.z *= gt; vh.w *= gt;
        *(float4*)(xl + c*64 + pp) = vl;
        *(float4*)(xh + c*64 + pp) = vh;
    }

    int ot = (t >> 4) << 2;
    int nb = (t & 15) << 2;

    // s0: (0=ql[xl,QS], 4=kl[xl])   s1: (1=kh[xh], 2=vh[xh])   s2: (5=vl[xl], 3=qh[xh,QS])
    const float* WA[3]; const float* WB[3];
    WA[0] = w_ql; WB[0] = w_kl;
    WA[1] = w_kh; WB[1] = w_vh;
    WA[2] = w_vl; WB[2] = w_qh;
    const int slotA[3] = {0, 1, 5};
    const int slotB[3] = {4, 2, 3};

    for (int s = 0; s < 3; s++) {
        __syncthreads();
        bool scaleA = (s == 0), scaleB = (s == 2);
        for (int i = t; i < 8192; i += 256) {
            int p = i >> 12, j = i & 4095;
            int o = j >> 6, c = j & 63;
            float wv = (p == 0) ? WA[s][j] : WB[s][j];
            if ((p == 0 && scaleA) || (p == 1 && scaleB)) wv *= QS;
            wb[p*4352 + c*WTS + o] = wv;
        }
        __syncthreads();

        const float* XA = (s == 2) ? xl : ((s == 0) ? xl : xh);
        const float* XB = (s == 2) ? xh : ((s == 0) ? xl : xh);
        bool sameX = (s != 2);

        u64 acc2[2][4][2];
        #pragma unroll
        for (int p = 0; p < 2; p++)
            #pragma unroll
            for (int n = 0; n < 4; n++) { acc2[p][n][0] = 0ULL; acc2[p][n][1] = 0ULL; }

        if (sameX) {
            #pragma unroll 4
            for (int c = 0; c < 64; c++) {
                float4 x4 = *(const float4*)(XA + c*64 + nb);
                u64 xd0 = pk2(x4.x, x4.x);
                u64 xd1 = pk2(x4.y, x4.y);
                u64 xd2 = pk2(x4.z, x4.z);
                u64 xd3 = pk2(x4.w, x4.w);
                #pragma unroll
                for (int p = 0; p < 2; p++) {
                    ulonglong2 w2v = *(const ulonglong2*)(wb + p*4352 + c*WTS + ot);
                    acc2[p][0][0] = fma2(xd0, w2v.x, acc2[p][0][0]);
                    acc2[p][0][1] = fma2(xd0, w2v.y, acc2[p][0][1]);
                    acc2[p][1][0] = fma2(xd1, w2v.x, acc2[p][1][0]);
                    acc2[p][1][1] = fma2(xd1, w2v.y, acc2[p][1][1]);
                    acc2[p][2][0] = fma2(xd2, w2v.x, acc2[p][2][0]);
                    acc2[p][2][1] = fma2(xd2, w2v.y, acc2[p][2][1]);
                    acc2[p][3][0] = fma2(xd3, w2v.x, acc2[p][3][0]);
                    acc2[p][3][1] = fma2(xd3, w2v.y, acc2[p][3][1]);
                }
            }
        } else {
            #pragma unroll 4
            for (int c = 0; c < 64; c++) {
                float4 xa4 = *(const float4*)(XA + c*64 + nb);
                float4 xb4 = *(const float4*)(XB + c*64 + nb);
                u64 xa0 = pk2(xa4.x, xa4.x), xa1 = pk2(xa4.y, xa4.y);
                u64 xa2 = pk2(xa4.z, xa4.z), xa3 = pk2(xa4.w, xa4.w);
                u64 xb0 = pk2(xb4.x, xb4.x), xb1 = pk2(xb4.y, xb4.y);
                u64 xb2 = pk2(xb4.z, xb4.z), xb3 = pk2(xb4.w, xb4.w);
                ulonglong2 wa = *(const ulonglong2*)(wb + c*WTS + ot);
                ulonglong2 wv = *(const ulonglong2*)(wb + 4352 + c*WTS + ot);
                acc2[0][0][0] = fma2(xa0, wa.x, acc2[0][0][0]);
                acc2[0][0][1] = fma2(xa0, wa.y, acc2[0][0][1]);
                acc2[0][1][0] = fma2(xa1, wa.x, acc2[0][1][0]);
                acc2[0][1][1] = fma2(xa1, wa.y, acc2[0][1][1]);
                acc2[0][2][0] = fma2(xa2, wa.x, acc2[0][2][0]);
                acc2[0][2][1] = fma2(xa2, wa.y, acc2[0][2][1]);
                acc2[0][3][0] = fma2(xa3, wa.x, acc2[0][3][0]);
                acc2[0][3][1] = fma2(xa3, wa.y, acc2[0][3][1]);
                acc2[1][0][0] = fma2(xb0, wv.x, acc2[1][0][0]);
                acc2[1][0][1] = fma2(xb0, wv.y, acc2[1][0][1]);
                acc2[1][1][0] = fma2(xb1, wv.x, acc2[1][1][0]);
                acc2[1][1][1] = fma2(xb1, wv.y, acc2[1][1][1]);
                acc2[1][2][0] = fma2(xb2, wv.x, acc2[1][2][0]);
                acc2[1][2][1] = fma2(xb2, wv.y, acc2[1][2][1]);
                acc2[1][3][0] = fma2(xb3, wv.x, acc2[1][3][0]);
                acc2[1][3][1] = fma2(xb3, wv.y, acc2[1][3][1]);
            }
        }

        int sl[2]; sl[0] = slotA[s]; sl[1] = slotB[s];
        #pragma unroll
        for (int p = 0; p < 2; p++) {
            float lo0[4], hi0[4], lo1[4], hi1[4];
            #pragma unroll
            for (int n = 0; n < 4; n++) {
                upk2(lo0[n], hi0[n], acc2[p][n][0]);
                upk2(lo1[n], hi1[n], acc2[p][n][1]);
            }
            size_t base = (size_t)sl[p]*NB*NC*NPIX + (size_t)(b*NC)*NPIX + pix0 + nb;
            *(float4*)(g_proj + base + (size_t)(ot+0)*NPIX) = make_float4(lo0[0],lo0[1],lo0[2],lo0[3]);
            *(float4*)(g_proj + base + (size_t)(ot+1)*NPIX) = make_float4(hi0[0],hi0[1],hi0[2],hi0[3]);
            *(float4*)(g_proj + base + (size_t)(ot+2)*NPIX) = make_float4(lo1[0],lo1[1],lo1[2],lo1[3]);
            *(float4*)(g_proj + base + (size_t)(ot+3)*NPIX) = make_float4(hi1[0],hi1[1],hi1[2],hi1[3]);
        }
    }
}

// ---------------- attention: tf32 MMA v3 ----------------
// K staged 1-term tf32 (stride 72: sig-permuted B-frag loads are bank-conflict-free),
// V staged 2-term (hi,lo) uint2 (stride 66). Q from gmem, 2-term per n-tile.
// QK = 2 MMA (qh,ql x K1t); AV = 2 MMA (P 1-term cvt x Vhi,Vlo).
// sigma permutation (from rounds 7/8, validated): S C-regs chain directly into AV B-frags.
#define KSTR 72
#define VSTR 66
#define KHSZ (16*KSTR)          // words per head (K)
#define VHSZ (16*VSTR)          // uint2 per head (V)
#define SMEM_ATTN_WORDS (4*KHSZ + 4*VHSZ*2 + 256)

__global__ void __launch_bounds__(128, 4) attn_kernel()
{
    extern __shared__ uint32_t smu[];
    uint32_t* kbuf = smu;                         // 4*KHSZ words
    uint2*    vbuf = (uint2*)(smu + 4*KHSZ);      // 4*VHSZ uint2
    float*    sinv = (float*)(smu + 4*KHSZ + 4*VHSZ*2);

    int t = threadIdx.x;
    int l = blockIdx.x, dir = blockIdx.y, b = blockIdx.z;
    int y0 = (l / NWIN) * 4, x0 = (l % NWIN) * 4;

    // stage + convert K (1-term) and V (2-term)
    for (int i4 = t; i4 < 2048; i4 += 128) {
        int p = i4 >> 10, rem = i4 & 1023;       // p: 0=k 1=v
        int slot = dir*3 + 1 + p;
        int c = rem >> 4, q4 = rem & 15;
        int r = q4 >> 1, cc = (q4 & 1) * 4;
        int n = r*8 + cc;
        int h = c >> 4, d = c & 15;
        size_t gi = ((size_t)slot*NB*NC + (size_t)(b*NC + c))*NPIX + (size_t)(y0 + r)*NW + x0 + cc;
        float4 v4 = *(const float4*)(g_proj + gi);
        if (p == 0) {
            uint32_t* dst = kbuf + h*KHSZ + d*KSTR + n;
            dst[0] = tf32r(v4.x);
            dst[1] = tf32r(v4.y);
            dst[2] = tf32r(v4.z);
            dst[3] = tf32r(v4.w);
        } else {
            uint2 e0, e1, e2, e3;
            tsplit(v4.x, e0.x, e0.y);
            tsplit(v4.y, e1.x, e1.y);
            tsplit(v4.z, e2.x, e2.y);
            tsplit(v4.w, e3.x, e3.y);
            uint2* dst = vbuf + h*VHSZ + d*VSTR + n;
            dst[0] = e0; dst[1] = e1; dst[2] = e2; dst[3] = e3;
        }
    }
    __syncthreads();

    int h = t >> 5, lane = t & 31;
    int gid = lane >> 2, tig = lane & 3;
    int sig = (gid & 1) ? ((gid >> 1) + 4) : (gid >> 1);   // sigma(gid)

    const uint32_t* kf = kbuf + h*KHSZ;
    const uint2*    vf = vbuf + h*VHSZ;
    const float* Qg = g_proj + ((size_t)(dir ? 3 : 0)*NB*NC + (size_t)(b*NC + h*16))*NPIX;
    float* gout = (dir ? g_acc_h : g_acc_l) + ((size_t)(b*NC + h*16))*NPIX;

    #pragma unroll
    for (int nt = 0; nt < 4; nt++) {
        int nbase = nt*16;
        size_t pA = (size_t)(y0 + 2*nt)*NW + x0 + gid;   // pixel for n = nbase+gid
        size_t pB = pA + NW;                              // pixel for n = nbase+gid+8

        // ---- Q A-fragments (hi/lo) from gmem, 2 d-chunks ----
        uint32_t qh[2][4], ql[2][4];
        #pragma unroll
        for (int kq = 0; kq < 2; kq++) {
            int d0 = kq*8 + tig;
            tsplit(Qg[(size_t)d0*NPIX     + pA], qh[kq][0], ql[kq][0]);
            tsplit(Qg[(size_t)d0*NPIX     + pB], qh[kq][1], ql[kq][1]);
            tsplit(Qg[(size_t)(d0+4)*NPIX + pA], qh[kq][2], ql[kq][2]);
            tsplit(Qg[(size_t)(d0+4)*NPIX + pB], qh[kq][3], ql[kq][3]);
        }

        float o0[4] = {0.f,0.f,0.f,0.f};   // O tile, n = nbase + 0..7
        float o1[4] = {0.f,0.f,0.f,0.f};   // O tile, n = nbase + 8..15
        float rs0 = 0.f, rs1 = 0.f;

        #pragma unroll
        for (int m8 = 0; m8 < 64; m8 += 8) {
            // ---- S tile [n16 x m8]: q 2-term x K 1-term = 2 MMA per kq ----
            float c[4] = {0.f,0.f,0.f,0.f};
            #pragma unroll
            for (int kq = 0; kq < 2; kq++) {
                uint32_t kk0 = kf[(kq*8+tig)*KSTR   + m8 + sig];
                uint32_t kk1 = kf[(kq*8+tig+4)*KSTR + m8 + sig];
                mma8(c, qh[kq], kk0, kk1);
                mma8(c, ql[kq], kk0, kk1);
            }
            // ---- exp, rowsum, P 1-term cvt ----
            float e0 = ex2(c[0]), e1 = ex2(c[1]), e2 = ex2(c[2]), e3 = ex2(c[3]);
            rs0 += e0 + e1;
            rs1 += e2 + e3;
            uint32_t p0 = tf32r(e0), p1 = tf32r(e1), p2 = tf32r(e2), p3 = tf32r(e3);
            // ---- V A-fragments (pre-converted 2-term) ----
            uint2 vv0 = vf[gid*VSTR     + m8 + tig    ];
            uint2 vv1 = vf[(gid+8)*VSTR + m8 + tig    ];
            uint2 vv2 = vf[gid*VSTR     + m8 + tig + 4];
            uint2 vv3 = vf[(gid+8)*VSTR + m8 + tig + 4];
            uint32_t vh[4] = {vv0.x, vv1.x, vv2.x, vv3.x};
            uint32_t vl[4] = {vv0.y, vv1.y, vv2.y, vv3.y};
            // ---- AV: O[d16 x n8] += V * P^T ----
            mma8(o0, vh, p0, p1);
            mma8(o0, vl, p0, p1);
            mma8(o1, vh, p2, p3);
            mma8(o1, vl, p2, p3);
        }
        // ---- softmax denominators: reduce across the 4 tig lanes ----
        rs0 += __shfl_xor_sync(0xffffffffu, rs0, 1);
        rs0 += __shfl_xor_sync(0xffffffffu, rs0, 2);
        rs1 += __shfl_xor_sync(0xffffffffu, rs1, 1);
        rs1 += __shfl_xor_sync(0xffffffffu, rs1, 2);
        if (tig == 0) {
            sinv[h*64 + nbase + gid]     = 1.f / rs0;
            sinv[h*64 + nbase + gid + 8] = 1.f / rs1;
        }
        __syncwarp();
        // ---- normalize + atomic fold ----
        #pragma unroll
        for (int jt = 0; jt < 2; jt++) {
            const float* ot = jt ? o1 : o0;
            int n0 = nbase + jt*8 + 2*tig;
            float inv0 = sinv[h*64 + n0];
            float inv1 = sinv[h*64 + n0 + 1];
            size_t pix0 = (size_t)(y0 + (n0 >> 3))*NW + x0 + (n0 & 7);
            size_t pix1 = (size_t)(y0 + ((n0+1) >> 3))*NW + x0 + ((n0+1) & 7);
            atomicAdd(gout + (size_t)gid*NPIX     + pix0, ot[0]*inv0);
            atomicAdd(gout + (size_t)gid*NPIX     + pix1, ot[1]*inv1);
            atomicAdd(gout + (size_t)(gid+8)*NPIX + pix0, ot[2]*inv0);
            atomicAdd(gout + (size_t)(gid+8)*NPIX + pix1, ot[3]*inv1);
        }
    }
}

// ---------------- epilogue: streaming (weights-only smem), 512 blocks ----------------
__device__ __forceinline__ int covdim(int y) {
    int imin = (y >= 8) ? ((y - 4) >> 2) : 0;
    int imax = y >> 2; if (imax > 30) imax = 30;
    return imax - imin + 1;
}

__global__ void __launch_bounds__(256) epi_kernel(
    const float* __restrict__ low, const float* __restrict__ high,
    const float* __restrict__ wpl, const float* __restrict__ wph,
    float* __restrict__ out)
{
    __shared__ float wl[64*WTS];
    __shared__ float wh[64*WTS];

    int t = threadIdx.x;
    int chunk = blockIdx.x;            // 512 chunks: 128 per batch, 128 pixels each
    int b = chunk >> 7;
    int pix0 = (chunk & 127) * 128;

    for (int i = t; i < 4096; i += 256) {
        int o = i >> 6, c = i & 63;
        wl[c*WTS + o] = wpl[i];
        wh[c*WTS + o] = wph[i];
    }
    __syncthreads();

    int px = t & 127, og = (t >> 7) * 32;
    int pix = pix0 + px;
    int y = pix >> 7, x = pix & 127;
    float ic = 1.f / ((float)covdim(y) * (float)covdim(x));

    const float* al = g_acc_l + (size_t)(b*NC)*NPIX + pix;
    const float* ah = g_acc_h + (size_t)(b*NC)*NPIX + pix;

    u64 rl2[16], rh2[16];
    #pragma unroll
    for (int j = 0; j < 16; j++) { rl2[j] = 0ULL; rh2[j] = 0ULL; }

    #pragma unroll 4
    for (int c = 0; c < 64; c++) {
        float tv = al[(size_t)c*NPIX] * ic;
        float hv = ah[(size_t)c*NPIX] * ic;
        u64 tv2 = pk2(tv, tv);
        u64 hv2 = pk2(hv, hv);
        const ulonglong2* wlr = (const ulonglong2*)(wl + c*WTS + og);
        const ulonglong2* whr = (const ulonglong2*)(wh + c*WTS + og);
        #pragma unroll
        for (int o4 = 0; o4 < 8; o4++) {
            ulonglong2 a2 = wlr[o4];
            ulonglong2 b2 = whr[o4];
            rl2[o4*2]   = fma2(tv2, a2.x, rl2[o4*2]);
            rl2[o4*2+1] = fma2(tv2, a2.y, rl2[o4*2+1]);
            rh2[o4*2]   = fma2(hv2, b2.x, rh2[o4*2]);
            rh2[o4*2+1] = fma2(hv2, b2.y, rh2[o4*2+1]);
        }
    }
    size_t half = (size_t)NB*NC*NPIX;
    #pragma unroll
    for (int j = 0; j < 16; j++) {
        float a, bb; upk2(a, bb, rl2[j]);
        float c2, d2; upk2(c2, d2, rh2[j]);
        int o0 = og + j*2;
        size_t gi0 = (size_t)(b*NC + o0)*NPIX + pix;
        size_t gi1 = (size_t)(b*NC + o0 + 1)*NPIX + pix;
        out[gi0]        = low[gi0]  + a;
        out[gi1]        = low[gi1]  + bb;
        out[half + gi0] = high[gi0] + c2;
        out[half + gi1] = high[gi1] + d2;
    }
}

extern "C" void kernel_launch(void* const* d_in, const int* in_sizes, int n_in,
                              void* d_out, int out_size)
{
    (void)in_sizes; (void)n_in; (void)out_size;
    const float* low  = (const float*)d_in[0];
    const float* high = (const float*)d_in[1];
    const float* w_ql = (const float*)d_in[2];
    const float* w_kh = (const float*)d_in[3];
    const float* w_vh = (const float*)d_in[4];
    const float* w_qh = (const float*)d_in[5];
    const float* w_kl = (const float*)d_in[6];
    const float* w_vl = (const float*)d_in[7];
    const float* wpl  = (const float*)d_in[8];
    const float* wph  = (const float*)d_in[9];

    void* pl; cudaGetSymbolAddress(&pl, g_acc_l);
    void* ph; cudaGetSymbolAddress(&ph, g_acc_h);
    cudaMemsetAsync(pl, 0, sizeof(float)*(size_t)NB*NC*NPIX);
    cudaMemsetAsync(ph, 0, sizeof(float)*(size_t)NB*NC*NPIX);

    int proj_smem = (8192 + 8704) * 4;        // 67.6 KB
    int attn_smem = SMEM_ATTN_WORDS * 4;      // ~53 KB

    cudaFuncSetAttribute(proj_kernel, cudaFuncAttributeMaxDynamicSharedMemorySize, proj_smem);
    cudaFuncSetAttribute(attn_kernel, cudaFuncAttributeMaxDynamicSharedMemorySize, attn_smem);

    mean_kernel<<<NB*NC, 256>>>(high);
    se_kernel<<<1, 256>>>((const float*)d_in[10], (const float*)d_in[11],
                          (const float*)d_in[12], (const float*)d_in[13],
                          (const float*)d_in[14], (const float*)d_in[15]);
    proj_kernel<<<dim3(NPIX/64, NB), 256, proj_smem>>>(low, high, w_ql, w_kh, w_vh, w_qh, w_kl, w_vl);
    attn_kernel<<<dim3(NL, 2, NB), 128, attn_smem>>>();
    epi_kernel<<<512, 256>>>(low, high, wpl, wph, (float*)d_out);
}

// round 12
// speedup vs baseline: 1.2948x; 1.0640x over previous
#include <cuda_runtime.h>
#include <cstdint>

#define NB 4
#define NC 64
#define NH 128
#define NW 128
#define NPIX (NH*NW)
#define NWIN 31
#define NL (NWIN*NWIN)

typedef unsigned long long u64;

// proj slot order: 0=ql 1=kh 2=vh 3=qh 4=kl 5=vl  (dir0 uses 0,1,2; dir1 uses 3,4,5)
__device__ float g_proj[6*NB*NC*NPIX];
__device__ float g_win_l[(size_t)NB*NL*64*64];   // [b][l][n][c] per-window outputs
__device__ float g_win_h[(size_t)NB*NL*64*64];
__device__ float g_mean[NB*NC];
__device__ float g_sgate[NB*NC];

// ---------------- packed f32x2 helpers ----------------
__device__ __forceinline__ u64 pk2(float lo, float hi) {
    u64 r;
    asm("mov.b64 %0,{%1,%2};" : "=l"(r) : "f"(lo), "f"(hi));
    return r;
}
__device__ __forceinline__ void upk2(float& lo, float& hi, u64 v) {
    asm("mov.b64 {%0,%1},%2;" : "=f"(lo), "=f"(hi) : "l"(v));
}
__device__ __forceinline__ u64 fma2(u64 a, u64 b, u64 c) {
    u64 d;
    asm("fma.rn.f32x2 %0,%1,%2,%3;" : "=l"(d) : "l"(a), "l"(b), "l"(c));
    return d;
}

// ---------------- tf32 mma helpers ----------------
__device__ __forceinline__ uint32_t tf32r(float f) {
    uint32_t r;
    asm("cvt.rna.tf32.f32 %0,%1;" : "=r"(r) : "f"(f));
    return r;
}
__device__ __forceinline__ float ex2(float x) {
    float r;
    asm("ex2.approx.f32 %0,%1;" : "=f"(r) : "f"(x));
    return r;
}
__device__ __forceinline__ void mma8(float* d, const uint32_t* a, uint32_t b0, uint32_t b1) {
    asm volatile(
        "mma.sync.aligned.m16n8k8.row.col.f32.tf32.tf32.f32 "
        "{%0,%1,%2,%3},{%4,%5,%6,%7},{%8,%9},{%0,%1,%2,%3};"
        : "+f"(d[0]), "+f"(d[1]), "+f"(d[2]), "+f"(d[3])
        : "r"(a[0]), "r"(a[1]), "r"(a[2]), "r"(a[3]), "r"(b0), "r"(b1));
}

// ---------------- SE: per-channel global mean ----------------
__global__ void mean_kernel(const float* __restrict__ high) {
    int bc = blockIdx.x;
    const float* p = high + (size_t)bc * NPIX;
    float s = 0.f;
    for (int i = threadIdx.x; i < NPIX; i += 256) s += p[i];
    __shared__ float red[256];
    red[threadIdx.x] = s; __syncthreads();
    for (int k = 128; k > 0; k >>= 1) {
        if (threadIdx.x < k) red[threadIdx.x] += red[threadIdx.x + k];
        __syncthreads();
    }
    if (threadIdx.x == 0) g_mean[bc] = red[0] * (1.f/NPIX);
}

// ---------------- SE: gate per (b,c) ----------------
__global__ void se_kernel(const float* __restrict__ w10, const float* __restrict__ w20,
                          const float* __restrict__ w11, const float* __restrict__ w21,
                          const float* __restrict__ w12, const float* __restrict__ w22) {
    int t = threadIdx.x;
    int b = t >> 6, c = t & 63;
    int g  = (c < 22) ? 0 : ((c < 43) ? 1 : 2);
    int of = (g == 0) ? 0 : ((g == 1) ? 22 : 43);
    int gc = (g == 0) ? 22 : 21;
    const float* w1 = (g==0) ? w10 : ((g==1) ? w11 : w12);
    const float* w2 = (g==0) ? w20 : ((g==1) ? w21 : w22);
    float h = 0.f;
    for (int j = 0; j < gc; j++) h += g_mean[b*64 + of + j] * w1[j];
    h = fmaxf(h, 0.f);
    float v = h * w2[c - of];
    g_sgate[t] = 1.f / (1.f + __expf(-v));
}

// ---------------- projections: 3 stages of 2 weights; 67KB smem -> 3 blocks/SM ----------------
#define WTS 68
#define QS 0.36067376022224085f
__global__ void __launch_bounds__(256,3) proj_kernel(
    const float* __restrict__ low, const float* __restrict__ high,
    const float* __restrict__ w_ql, const float* __restrict__ w_kh,
    const float* __restrict__ w_vh, const float* __restrict__ w_qh,
    const float* __restrict__ w_kl, const float* __restrict__ w_vl)
{
    extern __shared__ float sm[];
    float* xl = sm;            // 4096
    float* xh = sm + 4096;     // 4096
    float* wb = sm + 8192;     // 2 * 64*68 = 8704

    int t = threadIdx.x;
    int pix0 = blockIdx.x * 64;
    int b = blockIdx.y;

    for (int i4 = t; i4 < 1024; i4 += 256) {
        int c = i4 >> 4, pp = (i4 & 15) * 4;
        size_t gi = (size_t)(b*NC + c)*NPIX + pix0 + pp;
        float4 vl = *(const float4*)(low + gi);
        float4 vh = *(const float4*)(high + gi);
        float gt = g_sgate[b*64 + c];
        vh.x *= gt; vh.y *= gt; vh.z *= gt; vh.w *= gt;
        *(float4*)(xl + c*64 + pp) = vl;
        *(float4*)(xh + c*64 + pp) = vh;
    }

    int ot = (t >> 4) << 2;
    int nb = (t & 15) << 2;

    // s0: (0=ql[xl,QS], 4=kl[xl])   s1: (1=kh[xh], 2=vh[xh])   s2: (5=vl[xl], 3=qh[xh,QS])
    const float* WA[3]; const float* WB[3];
    WA[0] = w_ql; WB[0] = w_kl;
    WA[1] = w_kh; WB[1] = w_vh;
    WA[2] = w_vl; WB[2] = w_qh;
    const int slotA[3] = {0, 1, 5};
    const int slotB[3] = {4, 2, 3};

    for (int s = 0; s < 3; s++) {
        __syncthreads();
        bool scaleA = (s == 0), scaleB = (s == 2);
        for (int i = t; i < 8192; i += 256) {
            int p = i >> 12, j = i & 4095;
            int o = j >> 6, c = j & 63;
            float wv = (p == 0) ? WA[s][j] : WB[s][j];
            if ((p == 0 && scaleA) || (p == 1 && scaleB)) wv *= QS;
            wb[p*4352 + c*WTS + o] = wv;
        }
        __syncthreads();

        const float* XA = (s == 2) ? xl : ((s == 0) ? xl : xh);
        const float* XB = (s == 2) ? xh : ((s == 0) ? xl : xh);
        bool sameX = (s != 2);

        u64 acc2[2][4][2];
        #pragma unroll
        for (int p = 0; p < 2; p++)
            #pragma unroll
            for (int n = 0; n < 4; n++) { acc2[p][n][0] = 0ULL; acc2[p][n][1] = 0ULL; }

        if (sameX) {
            #pragma unroll 4
            for (int c = 0; c < 64; c++) {
                float4 x4 = *(const float4*)(XA + c*64 + nb);
                u64 xd0 = pk2(x4.x, x4.x);
                u64 xd1 = pk2(x4.y, x4.y);
                u64 xd2 = pk2(x4.z, x4.z);
                u64 xd3 = pk2(x4.w, x4.w);
                #pragma unroll
                for (int p = 0; p < 2; p++) {
                    ulonglong2 w2v = *(const ulonglong2*)(wb + p*4352 + c*WTS + ot);
                    acc2[p][0][0] = fma2(xd0, w2v.x, acc2[p][0][0]);
                    acc2[p][0][1] = fma2(xd0, w2v.y, acc2[p][0][1]);
                    acc2[p][1][0] = fma2(xd1, w2v.x, acc2[p][1][0]);
                    acc2[p][1][1] = fma2(xd1, w2v.y, acc2[p][1][1]);
                    acc2[p][2][0] = fma2(xd2, w2v.x, acc2[p][2][0]);
                    acc2[p][2][1] = fma2(xd2, w2v.y, acc2[p][2][1]);
                    acc2[p][3][0] = fma2(xd3, w2v.x, acc2[p][3][0]);
                    acc2[p][3][1] = fma2(xd3, w2v.y, acc2[p][3][1]);
                }
            }
        } else {
            #pragma unroll 4
            for (int c = 0; c < 64; c++) {
                float4 xa4 = *(const float4*)(XA + c*64 + nb);
                float4 xb4 = *(const float4*)(XB + c*64 + nb);
                u64 xa0 = pk2(xa4.x, xa4.x), xa1 = pk2(xa4.y, xa4.y);
                u64 xa2 = pk2(xa4.z, xa4.z), xa3 = pk2(xa4.w, xa4.w);
                u64 xb0 = pk2(xb4.x, xb4.x), xb1 = pk2(xb4.y, xb4.y);
                u64 xb2 = pk2(xb4.z, xb4.z), xb3 = pk2(xb4.w, xb4.w);
                ulonglong2 wa = *(const ulonglong2*)(wb + c*WTS + ot);
                ulonglong2 wv = *(const ulonglong2*)(wb + 4352 + c*WTS + ot);
                acc2[0][0][0] = fma2(xa0, wa.x, acc2[0][0][0]);
                acc2[0][0][1] = fma2(xa0, wa.y, acc2[0][0][1]);
                acc2[0][1][0] = fma2(xa1, wa.x, acc2[0][1][0]);
                acc2[0][1][1] = fma2(xa1, wa.y, acc2[0][1][1]);
                acc2[0][2][0] = fma2(xa2, wa.x, acc2[0][2][0]);
                acc2[0][2][1] = fma2(xa2, wa.y, acc2[0][2][1]);
                acc2[0][3][0] = fma2(xa3, wa.x, acc2[0][3][0]);
                acc2[0][3][1] = fma2(xa3, wa.y, acc2[0][3][1]);
                acc2[1][0][0] = fma2(xb0, wv.x, acc2[1][0][0]);
                acc2[1][0][1] = fma2(xb0, wv.y, acc2[1][0][1]);
                acc2[1][1][0] = fma2(xb1, wv.x, acc2[1][1][0]);
                acc2[1][1][1] = fma2(xb1, wv.y, acc2[1][1][1]);
                acc2[1][2][0] = fma2(xb2, wv.x, acc2[1][2][0]);
                acc2[1][2][1] = fma2(xb2, wv.y, acc2[1][2][1]);
                acc2[1][3][0] = fma2(xb3, wv.x, acc2[1][3][0]);
                acc2[1][3][1] = fma2(xb3, wv.y, acc2[1][3][1]);
            }
        }

        int sl[2]; sl[0] = slotA[s]; sl[1] = slotB[s];
        #pragma unroll
        for (int p = 0; p < 2; p++) {
            float lo0[4], hi0[4], lo1[4], hi1[4];
            #pragma unroll
            for (int n = 0; n < 4; n++) {
                upk2(lo0[n], hi0[n], acc2[p][n][0]);
                upk2(lo1[n], hi1[n], acc2[p][n][1]);
            }
            size_t base = (size_t)sl[p]*NB*NC*NPIX + (size_t)(b*NC)*NPIX + pix0 + nb;
            *(float4*)(g_proj + base + (size_t)(ot+0)*NPIX) = make_float4(lo0[0],lo0[1],lo0[2],lo0[3]);
            *(float4*)(g_proj + base + (size_t)(ot+1)*NPIX) = make_float4(hi0[0],hi0[1],hi0[2],hi0[3]);
            *(float4*)(g_proj + base + (size_t)(ot+2)*NPIX) = make_float4(lo1[0],lo1[1],lo1[2],lo1[3]);
            *(float4*)(g_proj + base + (size_t)(ot+3)*NPIX) = make_float4(hi1[0],hi1[1],hi1[2],hi1[3]);
        }
    }
}

// ---------------- attention: tf32 MMA v4 (all 1-term, STG fold) ----------------
// K stride 72: B-frag loads bank = 8*tig+sig, conflict-free.
// V stride 68: A-frag loads bank = 4*gid+tig, conflict-free.
// Outputs stored per-window (no atomics): g_win[b][l][n][c].
#define KSTR 72
#define VSTR 68
#define KHSZ (16*KSTR)
#define VHSZ (16*VSTR)
#define SMEM_ATTN_WORDS (4*KHSZ + 4*VHSZ + 256)

__global__ void __launch_bounds__(128, 5) attn_kernel()
{
    extern __shared__ uint32_t smu[];
    uint32_t* kbuf = smu;                      // 4*KHSZ
    uint32_t* vbuf = smu + 4*KHSZ;             // 4*VHSZ
    float*    sinv = (float*)(smu + 4*KHSZ + 4*VHSZ);   // 256

    int t = threadIdx.x;
    int l = blockIdx.x, dir = blockIdx.y, b = blockIdx.z;
    int y0 = (l / NWIN) * 4, x0 = (l % NWIN) * 4;

    // stage + convert K and V (1-term tf32)
    for (int i4 = t; i4 < 2048; i4 += 128) {
        int p = i4 >> 10, rem = i4 & 1023;       // p: 0=k 1=v
        int slot = dir*3 + 1 + p;
        int c = rem >> 4, q4 = rem & 15;
        int r = q4 >> 1, cc = (q4 & 1) * 4;
        int n = r*8 + cc;
        int h = c >> 4, d = c & 15;
        size_t gi = ((size_t)slot*NB*NC + (size_t)(b*NC + c))*NPIX + (size_t)(y0 + r)*NW + x0 + cc;
        float4 v4 = *(const float4*)(g_proj + gi);
        uint4 e;
        e.x = tf32r(v4.x); e.y = tf32r(v4.y); e.z = tf32r(v4.z); e.w = tf32r(v4.w);
        uint32_t* dst = (p ? (vbuf + h*VHSZ + d*VSTR) : (kbuf + h*KHSZ + d*KSTR)) + n;
        *(uint4*)dst = e;
    }
    __syncthreads();

    int h = t >> 5, lane = t & 31;
    int gid = lane >> 2, tig = lane & 3;
    int sig = (gid & 1) ? ((gid >> 1) + 4) : (gid >> 1);   // sigma(gid)

    const uint32_t* kf = kbuf + h*KHSZ;
    const uint32_t* vf = vbuf + h*VHSZ;
    const float* Qg = g_proj + ((size_t)(dir ? 3 : 0)*NB*NC + (size_t)(b*NC + h*16))*NPIX;
    float* wdst = (dir ? g_win_h : g_win_l) + (size_t)(b*NL + l)*4096;  // [n][c]

    #pragma unroll
    for (int nt = 0; nt < 4; nt++) {
        int nbase = nt*16;
        size_t pA = (size_t)(y0 + 2*nt)*NW + x0 + gid;   // pixel for n = nbase+gid
        size_t pB = pA + NW;                              // pixel for n = nbase+gid+8

        // ---- Q A-fragments (1-term) from gmem, 2 d-chunks ----
        uint32_t qh[2][4];
        #pragma unroll
        for (int kq = 0; kq < 2; kq++) {
            int d0 = kq*8 + tig;
            qh[kq][0] = tf32r(Qg[(size_t)d0*NPIX     + pA]);
            qh[kq][1] = tf32r(Qg[(size_t)d0*NPIX     + pB]);
            qh[kq][2] = tf32r(Qg[(size_t)(d0+4)*NPIX + pA]);
            qh[kq][3] = tf32r(Qg[(size_t)(d0+4)*NPIX + pB]);
        }

        float o0[4] = {0.f,0.f,0.f,0.f};   // O tile, n = nbase + 0..7
        float o1[4] = {0.f,0.f,0.f,0.f};   // O tile, n = nbase + 8..15
        float rs0 = 0.f, rs1 = 0.f;

        #pragma unroll
        for (int m8 = 0; m8 < 64; m8 += 8) {
            // ---- S tile [n16 x m8]: 2 MMA ----
            float c[4] = {0.f,0.f,0.f,0.f};
            #pragma unroll
            for (int kq = 0; kq < 2; kq++) {
                uint32_t kk0 = kf[(kq*8+tig)*KSTR   + m8 + sig];
                uint32_t kk1 = kf[(kq*8+tig+4)*KSTR + m8 + sig];
                mma8(c, qh[kq], kk0, kk1);
            }
            // ---- exp, rowsum, P 1-term ----
            float e0 = ex2(c[0]), e1 = ex2(c[1]), e2 = ex2(c[2]), e3 = ex2(c[3]);
            rs0 += e0 + e1;
            rs1 += e2 + e3;
            uint32_t p0 = tf32r(e0), p1 = tf32r(e1), p2 = tf32r(e2), p3 = tf32r(e3);
            // ---- V A-fragments (1-term, pre-converted) ----
            uint32_t va[4];
            va[0] = vf[gid*VSTR     + m8 + tig    ];
            va[1] = vf[(gid+8)*VSTR + m8 + tig    ];
            va[2] = vf[gid*VSTR     + m8 + tig + 4];
            va[3] = vf[(gid+8)*VSTR + m8 + tig + 4];
            // ---- AV: 2 MMA ----
            mma8(o0, va, p0, p1);
            mma8(o1, va, p2, p3);
        }
        // ---- softmax denominators: reduce across the 4 tig lanes ----
        rs0 += __shfl_xor_sync(0xffffffffu, rs0, 1);
        rs0 += __shfl_xor_sync(0xffffffffu, rs0, 2);
        rs1 += __shfl_xor_sync(0xffffffffu, rs1, 1);
        rs1 += __shfl_xor_sync(0xffffffffu, rs1, 2);
        if (tig == 0) {
            sinv[h*64 + nbase + gid]     = 1.f / rs0;
            sinv[h*64 + nbase + gid + 8] = 1.f / rs1;
        }
        __syncwarp();
        // ---- normalize + per-window store (no atomics) ----
        #pragma unroll
        for (int jt = 0; jt < 2; jt++) {
            const float* ot = jt ? o1 : o0;
            int n0 = nbase + jt*8 + 2*tig;
            float inv0 = sinv[h*64 + n0];
            float inv1 = sinv[h*64 + n0 + 1];
            float* w0 = wdst + (size_t)n0*64 + h*16;
            w0[gid]          = ot[0]*inv0;
            w0[64 + gid]     = ot[1]*inv1;
            w0[gid + 8]      = ot[2]*inv0;
            w0[64 + gid + 8] = ot[3]*inv1;
        }
    }
}

// ---------------- epilogue: gather <=4 windows per pixel, 1x1 proj + residual ----------------
__global__ void __launch_bounds__(256) epi_kernel(
    const float* __restrict__ low, const float* __restrict__ high,
    const float* __restrict__ wpl, const float* __restrict__ wph,
    float* __restrict__ out)
{
    extern __shared__ float sm[];
    float* tl = sm;                  // 64*65 = 4160
    float* th = sm + 4160;           // 4160
    float* wl = sm + 8320;           // 64*68 = 4352
    float* wh = sm + 8320 + 4352;    // 4352 (total 17024 floats)

    int t = threadIdx.x;
    int chunk = blockIdx.x;          // 1024 chunks: 256 per batch, 64 px each
    int b = chunk >> 8;
    int pix0 = (chunk & 255) * 64;

    for (int i = t; i < 4096; i += 256) {
        int o = i >> 6, c = i & 63;
        wl[c*WTS + o] = wpl[i];
        wh[c*WTS + o] = wph[i];
    }

    int cid = t & 63, pg = t >> 6;
    for (int it = 0; it < 16; it++) {
        int px = it*4 + pg;
        int pix = pix0 + px;
        int y = pix >> 7, x = pix & 127;
        int iyl = (y >= 8) ? ((y - 4) >> 2) : 0;
        int iyh = y >> 2; if (iyh > 30) iyh = 30;
        int ixl = (x >= 8) ? ((x - 4) >> 2) : 0;
        int ixh = x >> 2; if (ixh > 30) ixh = 30;
        float sl = 0.f, sh = 0.f;
        for (int iy = iyl; iy <= iyh; iy++) {
            for (int ix = ixl; ix <= ixh; ix++) {
                int ll = iy*NWIN + ix;
                int n = (y - 4*iy)*8 + (x - 4*ix);
                size_t base = ((size_t)(b*NL + ll)*64 + n)*64 + cid;
                sl += g_win_l[base];
                sh += g_win_h[base];
            }
        }
        float ic = 1.f / (float)((iyh - iyl + 1) * (ixh - ixl + 1));
        tl[cid*65 + px] = sl * ic;
        th[cid*65 + px] = sh * ic;
    }
    __syncthreads();

    int px = t & 63, og = (t >> 6) * 16;
    u64 rl2[8], rh2[8];
    #pragma unroll
    for (int j = 0; j < 8; j++) { rl2[j] = 0ULL; rh2[j] = 0ULL; }

    #pragma unroll 4
    for (int c = 0; c < 64; c++) {
        float tv = tl[c*65 + px];
        float hv = th[c*65 + px];
        u64 tv2 = pk2(tv, tv);
        u64 hv2 = pk2(hv, hv);
        const ulonglong2* wlr = (const ulonglong2*)(wl + c*WTS + og);
        const ulonglong2* whr = (const ulonglong2*)(wh + c*WTS + og);
        #pragma unroll
        for (int o4 = 0; o4 < 4; o4++) {
            ulonglong2 a2 = wlr[o4];
            ulonglong2 b2 = whr[o4];
            rl2[o4*2]   = fma2(tv2, a2.x, rl2[o4*2]);
            rl2[o4*2+1] = fma2(tv2, a2.y, rl2[o4*2+1]);
            rh2[o4*2]   = fma2(hv2, b2.x, rh2[o4*2]);
            rh2[o4*2+1] = fma2(hv2, b2.y, rh2[o4*2+1]);
        }
    }
    size_t half = (size_t)NB*NC*NPIX;
    int pix = pix0 + px;
    #pragma unroll
    for (int j = 0; j < 8; j++) {
        float a, bb; upk2(a, bb, rl2[j]);
        float c2, d2; upk2(c2, d2, rh2[j]);
        int o0 = og + j*2;
        size_t gi0 = (size_t)(b*NC + o0)*NPIX + pix;
        size_t gi1 = (size_t)(b*NC + o0 + 1)*NPIX + pix;
        out[gi0]        = low[gi0]  + a;
        out[gi1]        = low[gi1]  + bb;
        out[half + gi0] = high[gi0] + c2;
        out[half + gi1] = high[gi1] + d2;
    }
}

extern "C" void kernel_launch(void* const* d_in, const int* in_sizes, int n_in,
                              void* d_out, int out_size)
{
    (void)in_sizes; (void)n_in; (void)out_size;
    const float* low  = (const float*)d_in[0];
    const float* high = (const float*)d_in[1];
    const float* w_ql = (const float*)d_in[2];
    const float* w_kh = (const float*)d_in[3];
    const float* w_vh = (const float*)d_in[4];
    const float* w_qh = (const float*)d_in[5];
    const float* w_kl = (const float*)d_in[6];
    const float* w_vl = (const float*)d_in[7];
    const float* wpl  = (const float*)d_in[8];
    const float* wph  = (const float*)d_in[9];

    int proj_smem = (8192 + 8704) * 4;        // 67.6 KB
    int attn_smem = SMEM_ATTN_WORDS * 4;      // ~36.9 KB
    int epi_smem  = 17024 * 4;                // 66.5 KB

    cudaFuncSetAttribute(proj_kernel, cudaFuncAttributeMaxDynamicSharedMemorySize, proj_smem);
    cudaFuncSetAttribute(attn_kernel, cudaFuncAttributeMaxDynamicSharedMemorySize, attn_smem);
    cudaFuncSetAttribute(epi_kernel,  cudaFuncAttributeMaxDynamicSharedMemorySize, epi_smem);

    mean_kernel<<<NB*NC, 256>>>(high);
    se_kernel<<<1, 256>>>((const float*)d_in[10], (const float*)d_in[11],
                          (const float*)d_in[12], (const float*)d_in[13],
                          (const float*)d_in[14], (const float*)d_in[15]);
    proj_kernel<<<dim3(NPIX/64, NB), 256, proj_smem>>>(low, high, w_ql, w_kh, w_vh, w_qh, w_kl, w_vl);
    attn_kernel<<<dim3(NL, 2, NB), 128, attn_smem>>>();
    epi_kernel<<<1024, 256, epi_smem>>>(low, high, wpl, wph, (float*)d_out);
}